// round 3
// baseline (speedup 1.0000x reference)
#include <cuda_runtime.h>

#define N_NODES 100000
#define E_EDGES 1600000
#define DIMS    3
#define C_CH    32
#define ROW_IN  67   // DIM + F
#define ROW_OUT 35   // DIM + C
#define NB_SCAN 98   // ceil(N/1024)

// ---- scratch (static device globals; no allocation) ----
__device__ int    g_deg[N_NODES];
__device__ int    g_off[N_NODES + 1];
__device__ int    g_cursor[N_NODES];
__device__ int    g_bsum[NB_SCAN];
__device__ int    g_btop[NB_SCAN];
__device__ int    g_done;
__device__ volatile int g_flag;
__device__ float4 g_ch[N_NODES];        // {x, y, z, hsum}
__device__ float4 g_payload[E_EDGES];   // {u0,u1,u2,hsum[dst]} per CSR slot

__device__ __forceinline__ float ex2_approx(float x) {
    float r;
    asm("ex2.approx.f32 %0, %1;" : "=f"(r) : "f"(x));
    return r;
}
__device__ __forceinline__ float tanh_approx(float x) {
    float r;
    asm("tanh.approx.f32 %0, %1;" : "=f"(r) : "f"(x));
    return r;
}

// K1: one warp per node: hsum, coords->out, packed {coords,hsum}, deg=0
__global__ void k_init(const float* __restrict__ feat, float* __restrict__ out) {
    int gtid = blockIdx.x * blockDim.x + threadIdx.x;
    if (gtid == 0) { g_done = 0; g_flag = 0; }
    int node = gtid >> 5;
    int lane = gtid & 31;
    if (node >= N_NODES) return;
    const float* row = feat + (size_t)node * ROW_IN;
    float s = row[DIMS + lane] + row[DIMS + 32 + lane];
    #pragma unroll
    for (int o = 16; o > 0; o >>= 1) s += __shfl_xor_sync(0xffffffffu, s, o);
    if (lane == 0) {
        g_deg[node] = 0;
        g_ch[node] = make_float4(row[0], row[1], row[2], s);
    }
    if (lane < DIMS) out[(size_t)node * ROW_OUT + lane] = row[lane];
}

// K2: histogram of src
__global__ void k_hist(const int2* __restrict__ ei) {
    int e = blockIdx.x * blockDim.x + threadIdx.x;
    if (e >= E_EDGES) return;
    atomicAdd(&g_deg[ei[e].x], 1);
}

// K3: fused single-launch scan: per-block scan + last-block top scan + add-back
__global__ void k_scan() {
    __shared__ int wsum[32];
    __shared__ int s_last;
    int i = blockIdx.x * 1024 + threadIdx.x;
    int lane = threadIdx.x & 31;
    int wid  = threadIdx.x >> 5;

    int d = (i < N_NODES) ? g_deg[i] : 0;
    int x = d;
    #pragma unroll
    for (int o = 1; o < 32; o <<= 1) {
        int v = __shfl_up_sync(0xffffffffu, x, o);
        if (lane >= o) x += v;
    }
    if (lane == 31) wsum[wid] = x;
    __syncthreads();
    if (wid == 0) {
        int w = wsum[lane];
        #pragma unroll
        for (int o = 1; o < 32; o <<= 1) {
            int v = __shfl_up_sync(0xffffffffu, w, o);
            if (lane >= o) w += v;
        }
        wsum[lane] = w;
    }
    __syncthreads();
    int excl = x - d + (wid > 0 ? wsum[wid - 1] : 0);
    int blockTotal = wsum[31];

    // publish block total; last arriving block scans the tops
    if (threadIdx.x == 0) {
        g_bsum[blockIdx.x] = blockTotal;
        __threadfence();
        int done = atomicAdd(&g_done, 1);
        s_last = (done == NB_SCAN - 1) ? 1 : 0;
    }
    __syncthreads();
    if (s_last) {
        // 128-thread shared scan of the 98 block sums
        __shared__ int sh[128];
        int t = threadIdx.x;
        if (t < 128) {
            int v = (t < NB_SCAN) ? g_bsum[t] : 0;
            sh[t] = v;
        }
        __syncthreads();
        #pragma unroll
        for (int o = 1; o < 128; o <<= 1) {
            int u = (t < 128 && t >= o) ? sh[t - o] : 0;
            __syncthreads();
            if (t < 128) sh[t] += u;
            __syncthreads();
        }
        if (t < NB_SCAN) g_btop[t] = (t == 0) ? 0 : sh[t - 1];
        if (t == NB_SCAN - 1) g_off[N_NODES] = sh[t];
        __syncthreads();
        if (t == 0) { __threadfence(); g_flag = 1; }
    }
    if (threadIdx.x == 0) {
        while (g_flag == 0) {}
    }
    __syncthreads();
    __threadfence();

    if (i < N_NODES) {
        int o = excl + __ldcg(&g_btop[blockIdx.x]);
        g_off[i] = o;
        g_cursor[i] = o;
    }
}

// K4: per-edge (2 edges/thread): u = tanh((c_dst-c_src)@W + b); scatter to CSR slot
__global__ void k_scatter(const int2*  __restrict__ ei,
                          const float* __restrict__ w,
                          const float* __restrict__ b) {
    int t = blockIdx.x * blockDim.x + threadIdx.x;
    #pragma unroll
    for (int k = 0; k < 2; k++) {
        int e = t + k * (E_EDGES / 2);
        int2 sd = ei[e];
        float4 cs = g_ch[sd.x];
        float4 cd = g_ch[sd.y];
        float dx = cd.x - cs.x;
        float dy = cd.y - cs.y;
        float dz = cd.z - cs.z;
        float u0 = tanh_approx(fmaf(dz, w[6], fmaf(dy, w[3], fmaf(dx, w[0], b[0]))));
        float u1 = tanh_approx(fmaf(dz, w[7], fmaf(dy, w[4], fmaf(dx, w[1], b[1]))));
        float u2 = tanh_approx(fmaf(dz, w[8], fmaf(dy, w[5], fmaf(dx, w[2], b[2]))));
        int pos = atomicAdd(&g_cursor[sd.x], 1);
        g_payload[pos] = make_float4(u0, u1, u2, cd.w);
    }
}

// K5: one warp per node, lane = channel. Gaussian kernel weights + segment sum.
__global__ void k_main(const float* __restrict__ mu,
                       const float* __restrict__ sig,
                       float*       __restrict__ out) {
    int gtid = blockIdx.x * blockDim.x + threadIdx.x;
    int node = gtid >> 5;
    int lane = gtid & 31;    // channel
    if (node >= N_NODES) return;

    size_t bi = (size_t)lane * (size_t)N_NODES * 3 + (size_t)node * 3;
    float m0 = mu[bi + 0], m1 = mu[bi + 1], m2 = mu[bi + 2];
    const float NHL2E = -0.7213475204444817f;   // -0.5 * log2(e)
    float a0 = __fdividef(NHL2E, sig[bi + 0]);
    float a1 = __fdividef(NHL2E, sig[bi + 1]);
    float a2 = __fdividef(NHL2E, sig[bi + 2]);

    float acc = 0.0f;
    int j    = g_off[node];
    int jend = g_off[node + 1];
    // unrolled x4 for load MLP
    for (; j + 4 <= jend; j += 4) {
        float4 p0 = g_payload[j + 0];
        float4 p1 = g_payload[j + 1];
        float4 p2 = g_payload[j + 2];
        float4 p3 = g_payload[j + 3];
        float d0, d1, d2, s;
        d0 = p0.x - m0; d1 = p0.y - m1; d2 = p0.z - m2;
        s = fmaf(d2 * d2, a2, fmaf(d1 * d1, a1, d0 * d0 * a0));
        acc = fmaf(ex2_approx(s), p0.w, acc);
        d0 = p1.x - m0; d1 = p1.y - m1; d2 = p1.z - m2;
        s = fmaf(d2 * d2, a2, fmaf(d1 * d1, a1, d0 * d0 * a0));
        acc = fmaf(ex2_approx(s), p1.w, acc);
        d0 = p2.x - m0; d1 = p2.y - m1; d2 = p2.z - m2;
        s = fmaf(d2 * d2, a2, fmaf(d1 * d1, a1, d0 * d0 * a0));
        acc = fmaf(ex2_approx(s), p2.w, acc);
        d0 = p3.x - m0; d1 = p3.y - m1; d2 = p3.z - m2;
        s = fmaf(d2 * d2, a2, fmaf(d1 * d1, a1, d0 * d0 * a0));
        acc = fmaf(ex2_approx(s), p3.w, acc);
    }
    for (; j < jend; j++) {
        float4 p = g_payload[j];
        float d0 = p.x - m0;
        float d1 = p.y - m1;
        float d2 = p.z - m2;
        float s = fmaf(d2 * d2, a2, fmaf(d1 * d1, a1, d0 * d0 * a0));
        acc = fmaf(ex2_approx(s), p.w, acc);
    }
    out[(size_t)node * ROW_OUT + DIMS + lane] = acc;
}

extern "C" void kernel_launch(void* const* d_in, const int* in_sizes, int n_in,
                              void* d_out, int out_size) {
    const float* feat = (const float*)d_in[0];
    const int*   ei   = (const int*)d_in[1];
    const float* w    = (const float*)d_in[2];
    const float* b    = (const float*)d_in[3];
    const float* mu   = (const float*)d_in[4];
    const float* sig  = (const float*)d_in[5];
    float* out = (float*)d_out;

    int blkNodeWarps = (N_NODES * 32 + 255) / 256;   // 12500
    int blkEdges     = (E_EDGES + 255) / 256;        // 6250

    k_init<<<blkNodeWarps, 256>>>(feat, out);
    k_hist<<<blkEdges, 256>>>((const int2*)ei);
    k_scan<<<NB_SCAN, 1024>>>();
    k_scatter<<<(E_EDGES / 2 + 255) / 256, 256>>>((const int2*)ei, w, b);
    k_main<<<blkNodeWarps, 256>>>(mu, sig, out);
}

// round 4
// speedup vs baseline: 1.2493x; 1.2493x over previous
#include <cuda_runtime.h>

#define N_NODES 100000
#define E_EDGES 1600000
#define DIMS    3
#define C_CH    32
#define ROW_IN  67   // DIM + F
#define ROW_OUT 35   // DIM + C
#define NB_SCAN 98   // ceil(N/1024)
#define CHUNK   8    // channels per register tile in k_main

// ---- scratch (static device globals; no allocation) ----
__device__ int    g_deg[N_NODES];
__device__ int    g_loc[N_NODES];
__device__ int    g_off[N_NODES + 1];
__device__ int    g_cursor[N_NODES];
__device__ int    g_bsum[NB_SCAN];
__device__ int    g_btop[NB_SCAN];
__device__ float4 g_ch[N_NODES];        // {x, y, z, hsum}
__device__ float4 g_payload[E_EDGES];   // {u0,u1,u2,hsum[dst]} per CSR slot

__device__ __forceinline__ float ex2_approx(float x) {
    float r;
    asm("ex2.approx.f32 %0, %1;" : "=f"(r) : "f"(x));
    return r;
}
__device__ __forceinline__ float tanh_approx(float x) {
    float r;
    asm("tanh.approx.f32 %0, %1;" : "=f"(r) : "f"(x));
    return r;
}

// K1: one warp per node: hsum, coords->out, packed {coords,hsum}, deg=0
__global__ void k_init(const float* __restrict__ feat, float* __restrict__ out) {
    int gtid = blockIdx.x * blockDim.x + threadIdx.x;
    int node = gtid >> 5;
    int lane = gtid & 31;
    if (node >= N_NODES) return;
    const float* row = feat + (size_t)node * ROW_IN;
    float s = row[DIMS + lane] + row[DIMS + 32 + lane];
    #pragma unroll
    for (int o = 16; o > 0; o >>= 1) s += __shfl_xor_sync(0xffffffffu, s, o);
    if (lane == 0) {
        g_deg[node] = 0;
        g_ch[node] = make_float4(row[0], row[1], row[2], s);
    }
    if (lane < DIMS) out[(size_t)node * ROW_OUT + lane] = row[lane];
}

// K2: histogram of src
__global__ void k_hist(const int2* __restrict__ ei) {
    int e = blockIdx.x * blockDim.x + threadIdx.x;
    if (e >= E_EDGES) return;
    atomicAdd(&g_deg[ei[e].x], 1);
}

// K3a: per-block exclusive scan (1024 elems/block), block totals
__global__ void k_scan_part() {
    __shared__ int wsum[32];
    int i = blockIdx.x * 1024 + threadIdx.x;
    int lane = threadIdx.x & 31;
    int wid  = threadIdx.x >> 5;
    int d = (i < N_NODES) ? g_deg[i] : 0;
    int x = d;
    #pragma unroll
    for (int o = 1; o < 32; o <<= 1) {
        int v = __shfl_up_sync(0xffffffffu, x, o);
        if (lane >= o) x += v;
    }
    if (lane == 31) wsum[wid] = x;
    __syncthreads();
    if (wid == 0) {
        int w = wsum[lane];
        #pragma unroll
        for (int o = 1; o < 32; o <<= 1) {
            int v = __shfl_up_sync(0xffffffffu, w, o);
            if (lane >= o) w += v;
        }
        wsum[lane] = w;
    }
    __syncthreads();
    int excl = x - d + (wid > 0 ? wsum[wid - 1] : 0);
    if (i < N_NODES) g_loc[i] = excl;
    if (threadIdx.x == 1023) g_bsum[blockIdx.x] = wsum[31];
}

// K3b: scan the 98 block sums (tiny, 1 block)
__global__ void k_scan_tops() {
    __shared__ int sh[128];
    int t = threadIdx.x;
    int v = (t < NB_SCAN) ? g_bsum[t] : 0;
    sh[t] = v;
    __syncthreads();
    #pragma unroll
    for (int o = 1; o < 128; o <<= 1) {
        int u = (t >= o) ? sh[t - o] : 0;
        __syncthreads();
        sh[t] += u;
        __syncthreads();
    }
    if (t < NB_SCAN) {
        g_btop[t] = (t == 0) ? 0 : sh[t - 1];
        if (t == NB_SCAN - 1) g_off[N_NODES] = sh[t];
    }
}

// K3c: add block prefix -> final offsets + cursors
__global__ void k_scan_add() {
    int i = blockIdx.x * 1024 + threadIdx.x;
    if (i >= N_NODES) return;
    int o = g_loc[i] + g_btop[blockIdx.x];
    g_off[i] = o;
    g_cursor[i] = o;
}

// K4: per-edge (2 edges/thread): u = tanh((c_dst-c_src)@W + b); scatter to CSR slot
__global__ void k_scatter(const int2*  __restrict__ ei,
                          const float* __restrict__ w,
                          const float* __restrict__ b) {
    int t = blockIdx.x * blockDim.x + threadIdx.x;
    #pragma unroll
    for (int k = 0; k < 2; k++) {
        int e = t + k * (E_EDGES / 2);
        int2 sd = ei[e];
        float4 cs = g_ch[sd.x];
        float4 cd = g_ch[sd.y];
        float dx = cd.x - cs.x;
        float dy = cd.y - cs.y;
        float dz = cd.z - cs.z;
        float u0 = tanh_approx(fmaf(dz, w[6], fmaf(dy, w[3], fmaf(dx, w[0], b[0]))));
        float u1 = tanh_approx(fmaf(dz, w[7], fmaf(dy, w[4], fmaf(dx, w[1], b[1]))));
        float u2 = tanh_approx(fmaf(dz, w[8], fmaf(dy, w[5], fmaf(dx, w[2], b[2]))));
        int pos = atomicAdd(&g_cursor[sd.x], 1);
        g_payload[pos] = make_float4(u0, u1, u2, cd.w);
    }
}

// K5: lane = node (coalesced mu/sig), channels processed in register tiles of 8.
// Payload CSR range for a block (~64KB) stays L1-resident across the 4 chunks.
__global__ void __launch_bounds__(256) k_main(const float* __restrict__ mu,
                                              const float* __restrict__ sig,
                                              float*       __restrict__ out) {
    int node = blockIdx.x * 256 + threadIdx.x;
    bool valid = node < N_NODES;
    int j0 = 0, j1 = 0;
    if (valid) { j0 = g_off[node]; j1 = g_off[node + 1]; }

    const float NHL2E = -0.7213475204444817f;   // -0.5 * log2(e)

    for (int chunk = 0; chunk < C_CH / CHUNK; chunk++) {
        float m0[CHUNK], m1[CHUNK], m2[CHUNK];
        float a0[CHUNK], a1[CHUNK], a2[CHUNK];
        float acc[CHUNK];
        #pragma unroll
        for (int c = 0; c < CHUNK; c++) {
            int ch = chunk * CHUNK + c;
            size_t bi = (size_t)ch * (size_t)N_NODES * 3 + (size_t)(valid ? node : 0) * 3;
            m0[c] = __ldg(&mu[bi + 0]);
            m1[c] = __ldg(&mu[bi + 1]);
            m2[c] = __ldg(&mu[bi + 2]);
            a0[c] = __fdividef(NHL2E, __ldg(&sig[bi + 0]));
            a1[c] = __fdividef(NHL2E, __ldg(&sig[bi + 1]));
            a2[c] = __fdividef(NHL2E, __ldg(&sig[bi + 2]));
            acc[c] = 0.0f;
        }
        for (int j = j0; j < j1; j++) {
            float4 p = __ldg(&g_payload[j]);
            #pragma unroll
            for (int c = 0; c < CHUNK; c++) {
                float d0 = p.x - m0[c];
                float d1 = p.y - m1[c];
                float d2 = p.z - m2[c];
                float s = fmaf(d2 * d2, a2[c], fmaf(d1 * d1, a1[c], d0 * d0 * a0[c]));
                acc[c] = fmaf(ex2_approx(s), p.w, acc[c]);
            }
        }
        if (valid) {
            float* o = out + (size_t)node * ROW_OUT + DIMS + chunk * CHUNK;
            #pragma unroll
            for (int c = 0; c < CHUNK; c++) o[c] = acc[c];
        }
    }
}

extern "C" void kernel_launch(void* const* d_in, const int* in_sizes, int n_in,
                              void* d_out, int out_size) {
    const float* feat = (const float*)d_in[0];
    const int*   ei   = (const int*)d_in[1];
    const float* w    = (const float*)d_in[2];
    const float* b    = (const float*)d_in[3];
    const float* mu   = (const float*)d_in[4];
    const float* sig  = (const float*)d_in[5];
    float* out = (float*)d_out;

    int blkNodeWarps = (N_NODES * 32 + 255) / 256;   // 12500
    int blkEdges     = (E_EDGES + 255) / 256;        // 6250
    int blkNodes     = (N_NODES + 255) / 256;        // 391

    k_init<<<blkNodeWarps, 256>>>(feat, out);
    k_hist<<<blkEdges, 256>>>((const int2*)ei);
    k_scan_part<<<NB_SCAN, 1024>>>();
    k_scan_tops<<<1, 128>>>();
    k_scan_add<<<NB_SCAN, 1024>>>();
    k_scatter<<<(E_EDGES / 2 + 255) / 256, 256>>>((const int2*)ei, w, b);
    k_main<<<blkNodes, 256>>>(mu, sig, out);
}

// round 5
// speedup vs baseline: 1.3335x; 1.0674x over previous
#include <cuda_runtime.h>

#define N_NODES 100000
#define E_EDGES 1600000
#define DIMS    3
#define C_CH    32
#define ROW_IN  67   // DIM + F
#define ROW_OUT 35   // DIM + C
#define NB_SCAN 98   // ceil(N/1024)
#define CHUNK   8    // channels per register tile in k_main

// ---- scratch (static device globals; no allocation) ----
// g_deg is zero at module load and re-zeroed by k_main each run.
__device__ int    g_deg[N_NODES];
__device__ int    g_start[N_NODES];
__device__ int    g_cursor[N_NODES];
__device__ int    g_alloc;
__device__ float4 g_ch[N_NODES];        // {x, y, z, hsum}
__device__ float4 g_payload[E_EDGES];   // {u0,u1,u2,hsum[dst]} per CSR slot

__device__ __forceinline__ float ex2_approx(float x) {
    float r;
    asm("ex2.approx.f32 %0, %1;" : "=f"(r) : "f"(x));
    return r;
}
__device__ __forceinline__ float tanh_approx(float x) {
    float r;
    asm("tanh.approx.f32 %0, %1;" : "=f"(r) : "f"(x));
    return r;
}

// K1: warp per node: hsum, coords->out, packed {coords,hsum}.
// First E threads ALSO histogram one edge each (g_deg arrives zeroed:
// zero-init at load, re-zeroed by k_main at the end of every run).
__global__ void k_init(const float* __restrict__ feat,
                       const int2*  __restrict__ ei,
                       float*       __restrict__ out) {
    int gtid = blockIdx.x * blockDim.x + threadIdx.x;
    if (gtid == 0) g_alloc = 0;
    if (gtid < E_EDGES) atomicAdd(&g_deg[ei[gtid].x], 1);

    int node = gtid >> 5;
    int lane = gtid & 31;
    if (node >= N_NODES) return;
    const float* row = feat + (size_t)node * ROW_IN;
    float s = row[DIMS + lane] + row[DIMS + 32 + lane];
    #pragma unroll
    for (int o = 16; o > 0; o >>= 1) s += __shfl_xor_sync(0xffffffffu, s, o);
    if (lane == 0) g_ch[node] = make_float4(row[0], row[1], row[2], s);
    if (lane < DIMS) out[(size_t)node * ROW_OUT + lane] = row[lane];
}

// K2: one-launch segment allocation: per-block scan + atomic block base.
// Offsets are not globally monotone across blocks — CSR only needs each
// node's own contiguous range [start, start+deg).
__global__ void k_alloc() {
    __shared__ int wsum[32];
    __shared__ int s_base;
    int i = blockIdx.x * 1024 + threadIdx.x;
    int lane = threadIdx.x & 31;
    int wid  = threadIdx.x >> 5;
    int d = (i < N_NODES) ? g_deg[i] : 0;
    int x = d;
    #pragma unroll
    for (int o = 1; o < 32; o <<= 1) {
        int v = __shfl_up_sync(0xffffffffu, x, o);
        if (lane >= o) x += v;
    }
    if (lane == 31) wsum[wid] = x;
    __syncthreads();
    if (wid == 0) {
        int w = wsum[lane];
        #pragma unroll
        for (int o = 1; o < 32; o <<= 1) {
            int v = __shfl_up_sync(0xffffffffu, w, o);
            if (lane >= o) w += v;
        }
        wsum[lane] = w;
    }
    __syncthreads();
    if (threadIdx.x == 0) s_base = atomicAdd(&g_alloc, wsum[31]);
    __syncthreads();
    int excl = x - d + (wid > 0 ? wsum[wid - 1] : 0);
    if (i < N_NODES) {
        int st = s_base + excl;
        g_start[i]  = st;
        g_cursor[i] = st;
    }
}

// K3: per-edge (4 edges/thread): u = tanh((c_dst-c_src)@W + b); scatter to slot
__global__ void k_scatter(const int2*  __restrict__ ei,
                          const float* __restrict__ w,
                          const float* __restrict__ b) {
    int t = blockIdx.x * blockDim.x + threadIdx.x;
    if (t >= E_EDGES / 4) return;
    #pragma unroll
    for (int k = 0; k < 4; k++) {
        int e = t + k * (E_EDGES / 4);
        int2 sd = ei[e];
        float4 cs = __ldg(&g_ch[sd.x]);
        float4 cd = __ldg(&g_ch[sd.y]);
        float dx = cd.x - cs.x;
        float dy = cd.y - cs.y;
        float dz = cd.z - cs.z;
        float u0 = tanh_approx(fmaf(dz, w[6], fmaf(dy, w[3], fmaf(dx, w[0], b[0]))));
        float u1 = tanh_approx(fmaf(dz, w[7], fmaf(dy, w[4], fmaf(dx, w[1], b[1]))));
        float u2 = tanh_approx(fmaf(dz, w[8], fmaf(dy, w[5], fmaf(dx, w[2], b[2]))));
        int pos = atomicAdd(&g_cursor[sd.x], 1);
        g_payload[pos] = make_float4(u0, u1, u2, cd.w);
    }
}

// K4: lane = node (coalesced mu/sig), channels in register tiles of 8.
// Gaussian expanded: s = Σ_r a_r u_r^2 + b_r u_r + c  (7-FFMA chain + EX2).
// Also re-zeroes g_deg for the next graph replay.
__global__ void __launch_bounds__(256) k_main(const float* __restrict__ mu,
                                              const float* __restrict__ sig,
                                              float*       __restrict__ out) {
    int node = blockIdx.x * 256 + threadIdx.x;
    bool valid = node < N_NODES;
    int j0 = 0, j1 = 0;
    if (valid) {
        j0 = g_start[node];
        j1 = j0 + g_deg[node];
        g_deg[node] = 0;            // reset for next replay
    }

    const float NHL2E = -0.7213475204444817f;   // -0.5 * log2(e)

    for (int chunk = 0; chunk < C_CH / CHUNK; chunk++) {
        float a0[CHUNK], a1[CHUNK], a2[CHUNK];
        float b0[CHUNK], b1[CHUNK], b2[CHUNK];
        float cc[CHUNK], acc[CHUNK];
        #pragma unroll
        for (int c = 0; c < CHUNK; c++) {
            int ch = chunk * CHUNK + c;
            size_t bi = (size_t)ch * (size_t)N_NODES * 3 + (size_t)(valid ? node : 0) * 3;
            float mm0 = __ldg(&mu[bi + 0]);
            float mm1 = __ldg(&mu[bi + 1]);
            float mm2 = __ldg(&mu[bi + 2]);
            a0[c] = __fdividef(NHL2E, __ldg(&sig[bi + 0]));
            a1[c] = __fdividef(NHL2E, __ldg(&sig[bi + 1]));
            a2[c] = __fdividef(NHL2E, __ldg(&sig[bi + 2]));
            b0[c] = -2.0f * a0[c] * mm0;
            b1[c] = -2.0f * a1[c] * mm1;
            b2[c] = -2.0f * a2[c] * mm2;
            cc[c] = fmaf(a2[c], mm2 * mm2, fmaf(a1[c], mm1 * mm1, a0[c] * mm0 * mm0));
            acc[c] = 0.0f;
        }
        for (int j = j0; j < j1; j++) {
            float4 p = __ldg(&g_payload[j]);
            float q0 = p.x * p.x;
            float q1 = p.y * p.y;
            float q2 = p.z * p.z;
            #pragma unroll
            for (int c = 0; c < CHUNK; c++) {
                float s = fmaf(a0[c], q0, cc[c]);
                s = fmaf(b0[c], p.x, s);
                s = fmaf(a1[c], q1, s);
                s = fmaf(b1[c], p.y, s);
                s = fmaf(a2[c], q2, s);
                s = fmaf(b2[c], p.z, s);
                acc[c] = fmaf(ex2_approx(s), p.w, acc[c]);
            }
        }
        if (valid) {
            float* o = out + (size_t)node * ROW_OUT + DIMS + chunk * CHUNK;
            #pragma unroll
            for (int c = 0; c < CHUNK; c++) o[c] = acc[c];
        }
    }
}

extern "C" void kernel_launch(void* const* d_in, const int* in_sizes, int n_in,
                              void* d_out, int out_size) {
    const float* feat = (const float*)d_in[0];
    const int*   ei   = (const int*)d_in[1];
    const float* w    = (const float*)d_in[2];
    const float* b    = (const float*)d_in[3];
    const float* mu   = (const float*)d_in[4];
    const float* sig  = (const float*)d_in[5];
    float* out = (float*)d_out;

    int blkNodeWarps = (N_NODES * 32 + 255) / 256;       // 12500
    int blkScatter   = (E_EDGES / 4 + 255) / 256;        // 1563
    int blkNodes     = (N_NODES + 255) / 256;            // 391

    k_init<<<blkNodeWarps, 256>>>(feat, (const int2*)ei, out);
    k_alloc<<<NB_SCAN, 1024>>>();
    k_scatter<<<blkScatter, 256>>>((const int2*)ei, w, b);
    k_main<<<blkNodes, 256>>>(mu, sig, out);
}

// round 7
// speedup vs baseline: 1.4650x; 1.0986x over previous
#include <cuda_runtime.h>

#define N_NODES 100000
#define E_EDGES 1600000
#define DIMS    3
#define C_CH    32
#define ROW_IN  67   // DIM + F
#define ROW_OUT 35   // DIM + C
#define NB_SCAN 98   // ceil(N/1024)
#define CHUNK   8    // channels per chunk-thread in k_main
#define NODES_PER_BLK 64

typedef unsigned long long u64;

// ---- scratch (static device globals; no allocation) ----
// g_deg is zero at module load and re-zeroed by k_main each run.
__device__ int    g_deg[N_NODES];
__device__ int    g_start[N_NODES];
__device__ int    g_cursor[N_NODES];   // after k_scatter: start+deg (segment end)
__device__ int    g_alloc;
__device__ float4 g_ch[N_NODES];        // {x, y, z, hsum}
__device__ float4 g_payload[E_EDGES];   // {u0,u1,u2,hsum[dst]} per CSR slot

__device__ __forceinline__ float ex2_approx(float x) {
    float r;
    asm("ex2.approx.f32 %0, %1;" : "=f"(r) : "f"(x));
    return r;
}
__device__ __forceinline__ float tanh_approx(float x) {
    float r;
    asm("tanh.approx.f32 %0, %1;" : "=f"(r) : "f"(x));
    return r;
}
__device__ __forceinline__ u64 pack2(float lo, float hi) {
    u64 r; asm("mov.b64 %0, {%1, %2};" : "=l"(r) : "f"(lo), "f"(hi)); return r;
}
__device__ __forceinline__ void unpack2(u64 v, float& lo, float& hi) {
    asm("mov.b64 {%0, %1}, %2;" : "=f"(lo), "=f"(hi) : "l"(v));
}
__device__ __forceinline__ u64 fma2(u64 a, u64 b, u64 c) {
    u64 d; asm("fma.rn.f32x2 %0, %1, %2, %3;" : "=l"(d) : "l"(a), "l"(b), "l"(c)); return d;
}
__device__ __forceinline__ u64 mul2(u64 a, u64 b) {
    u64 d; asm("mul.rn.f32x2 %0, %1, %2;" : "=l"(d) : "l"(a), "l"(b)); return d;
}

// K1: warp per node: hsum, coords->out, packed {coords,hsum}.
// First E threads ALSO histogram one edge each (g_deg arrives zeroed:
// zero-init at load, re-zeroed by k_main at the end of every run).
__global__ void k_init(const float* __restrict__ feat,
                       const int2*  __restrict__ ei,
                       float*       __restrict__ out) {
    int gtid = blockIdx.x * blockDim.x + threadIdx.x;
    if (gtid == 0) g_alloc = 0;
    if (gtid < E_EDGES) atomicAdd(&g_deg[ei[gtid].x], 1);

    int node = gtid >> 5;
    int lane = gtid & 31;
    if (node >= N_NODES) return;
    const float* row = feat + (size_t)node * ROW_IN;
    float s = row[DIMS + lane] + row[DIMS + 32 + lane];
    #pragma unroll
    for (int o = 16; o > 0; o >>= 1) s += __shfl_xor_sync(0xffffffffu, s, o);
    if (lane == 0) g_ch[node] = make_float4(row[0], row[1], row[2], s);
    if (lane < DIMS) out[(size_t)node * ROW_OUT + lane] = row[lane];
}

// K2: one-launch segment allocation: per-block scan + atomic block base.
__global__ void k_alloc() {
    __shared__ int wsum[32];
    __shared__ int s_base;
    int i = blockIdx.x * 1024 + threadIdx.x;
    int lane = threadIdx.x & 31;
    int wid  = threadIdx.x >> 5;
    int d = (i < N_NODES) ? g_deg[i] : 0;
    int x = d;
    #pragma unroll
    for (int o = 1; o < 32; o <<= 1) {
        int v = __shfl_up_sync(0xffffffffu, x, o);
        if (lane >= o) x += v;
    }
    if (lane == 31) wsum[wid] = x;
    __syncthreads();
    if (wid == 0) {
        int w = wsum[lane];
        #pragma unroll
        for (int o = 1; o < 32; o <<= 1) {
            int v = __shfl_up_sync(0xffffffffu, w, o);
            if (lane >= o) w += v;
        }
        wsum[lane] = w;
    }
    __syncthreads();
    if (threadIdx.x == 0) s_base = atomicAdd(&g_alloc, wsum[31]);
    __syncthreads();
    int excl = x - d + (wid > 0 ? wsum[wid - 1] : 0);
    if (i < N_NODES) {
        int st = s_base + excl;
        g_start[i]  = st;
        g_cursor[i] = st;
    }
}

// K3: per-edge (4 edges/thread): u = tanh((c_dst-c_src)@W + b); scatter to slot
__global__ void k_scatter(const int2*  __restrict__ ei,
                          const float* __restrict__ w,
                          const float* __restrict__ b) {
    int t = blockIdx.x * blockDim.x + threadIdx.x;
    if (t >= E_EDGES / 4) return;
    #pragma unroll
    for (int k = 0; k < 4; k++) {
        int e = t + k * (E_EDGES / 4);
        int2 sd = ei[e];
        float4 cs = __ldg(&g_ch[sd.x]);
        float4 cd = __ldg(&g_ch[sd.y]);
        float dx = cd.x - cs.x;
        float dy = cd.y - cs.y;
        float dz = cd.z - cs.z;
        float u0 = tanh_approx(fmaf(dz, w[6], fmaf(dy, w[3], fmaf(dx, w[0], b[0]))));
        float u1 = tanh_approx(fmaf(dz, w[7], fmaf(dy, w[4], fmaf(dx, w[1], b[1]))));
        float u2 = tanh_approx(fmaf(dz, w[8], fmaf(dy, w[5], fmaf(dx, w[2], b[2]))));
        int pos = atomicAdd(&g_cursor[sd.x], 1);
        g_payload[pos] = make_float4(u0, u1, u2, cd.w);
    }
}

// K4: block = 64 nodes x 4 chunk-threads. Each warp: 32 consecutive nodes at
// one uniform chunk of 8 channels -> mu/sig warp-coalesced, payload L1-shared.
// Loop bounds come from g_start / g_cursor (== start+deg after k_scatter), so
// g_deg is only WRITTEN here (reset for next replay) — no cross-warp race.
__global__ void __launch_bounds__(256) k_main(const float* __restrict__ mu,
                                              const float* __restrict__ sig,
                                              float*       __restrict__ out) {
    int node  = blockIdx.x * NODES_PER_BLK + (threadIdx.x & (NODES_PER_BLK - 1));
    int chunk = threadIdx.x / NODES_PER_BLK;          // 0..3
    bool valid = node < N_NODES;
    int nd = valid ? node : 0;

    int j0 = 0, j1 = 0;
    if (valid) {
        j0 = g_start[nd];
        j1 = g_cursor[nd];                            // segment end
        if (chunk == 0) g_deg[nd] = 0;                // reset for next replay
    }

    const float NHL2E = -0.7213475204444817f;         // -0.5 * log2(e)

    // load 8 channels' coefficients, pack into 4 f32x2 pairs
    u64 a0p[4], a1p[4], a2p[4], b0p[4], b1p[4], b2p[4], ccp[4], accp[4];
    #pragma unroll
    for (int c = 0; c < 4; c++) {
        float a0[2], a1[2], a2[2], bb0[2], bb1[2], bb2[2], cc[2];
        #pragma unroll
        for (int h = 0; h < 2; h++) {
            int ch = chunk * CHUNK + c * 2 + h;
            size_t bi = (size_t)ch * (size_t)N_NODES * 3 + (size_t)nd * 3;
            float m0 = __ldg(&mu[bi + 0]);
            float m1 = __ldg(&mu[bi + 1]);
            float m2 = __ldg(&mu[bi + 2]);
            a0[h] = __fdividef(NHL2E, __ldg(&sig[bi + 0]));
            a1[h] = __fdividef(NHL2E, __ldg(&sig[bi + 1]));
            a2[h] = __fdividef(NHL2E, __ldg(&sig[bi + 2]));
            bb0[h] = -2.0f * a0[h] * m0;
            bb1[h] = -2.0f * a1[h] * m1;
            bb2[h] = -2.0f * a2[h] * m2;
            cc[h]  = fmaf(a2[h], m2 * m2, fmaf(a1[h], m1 * m1, a0[h] * m0 * m0));
        }
        a0p[c] = pack2(a0[0], a0[1]);
        a1p[c] = pack2(a1[0], a1[1]);
        a2p[c] = pack2(a2[0], a2[1]);
        b0p[c] = pack2(bb0[0], bb0[1]);
        b1p[c] = pack2(bb1[0], bb1[1]);
        b2p[c] = pack2(bb2[0], bb2[1]);
        ccp[c] = pack2(cc[0], cc[1]);
        accp[c] = 0ull;
    }

    for (int j = j0; j < j1; j++) {
        float4 p = __ldg(&g_payload[j]);
        u64 px = pack2(p.x, p.x);
        u64 py = pack2(p.y, p.y);
        u64 pz = pack2(p.z, p.z);
        u64 pw = pack2(p.w, p.w);
        u64 q0 = mul2(px, px);
        u64 q1 = mul2(py, py);
        u64 q2 = mul2(pz, pz);
        #pragma unroll
        for (int c = 0; c < 4; c++) {
            u64 s = fma2(a0p[c], q0, ccp[c]);
            s = fma2(b0p[c], px, s);
            s = fma2(a1p[c], q1, s);
            s = fma2(b1p[c], py, s);
            s = fma2(a2p[c], q2, s);
            s = fma2(b2p[c], pz, s);
            float slo, shi;
            unpack2(s, slo, shi);
            u64 e = pack2(ex2_approx(slo), ex2_approx(shi));
            accp[c] = fma2(e, pw, accp[c]);
        }
    }

    if (valid) {
        float* o = out + (size_t)node * ROW_OUT + DIMS + chunk * CHUNK;
        #pragma unroll
        for (int c = 0; c < 4; c++) {
            float lo, hi;
            unpack2(accp[c], lo, hi);
            o[c * 2 + 0] = lo;
            o[c * 2 + 1] = hi;
        }
    }
}

extern "C" void kernel_launch(void* const* d_in, const int* in_sizes, int n_in,
                              void* d_out, int out_size) {
    const float* feat = (const float*)d_in[0];
    const int*   ei   = (const int*)d_in[1];
    const float* w    = (const float*)d_in[2];
    const float* b    = (const float*)d_in[3];
    const float* mu   = (const float*)d_in[4];
    const float* sig  = (const float*)d_in[5];
    float* out = (float*)d_out;

    int blkNodeWarps = (N_NODES * 32 + 255) / 256;                 // 12500
    int blkScatter   = (E_EDGES / 4 + 255) / 256;                  // 1563
    int blkMain      = (N_NODES + NODES_PER_BLK - 1) / NODES_PER_BLK; // 1563

    k_init<<<blkNodeWarps, 256>>>(feat, (const int2*)ei, out);
    k_alloc<<<NB_SCAN, 1024>>>();
    k_scatter<<<blkScatter, 256>>>((const int2*)ei, w, b);
    k_main<<<blkMain, 256>>>(mu, sig, out);
}